// round 1
// baseline (speedup 1.0000x reference)
#include <cuda_runtime.h>

#define NPIX  65536
#define HW4K  4096
#define CIN   256
#define FINT  128
#define KCH   16

// Scratch (device globals — no runtime allocation allowed)
__device__ float d_Yg[FINT * NPIX];      // 33.5 MB
__device__ float d_Yx[FINT * NPIX];      // 33.5 MB
__device__ float d_S[NPIX];
__device__ float d_stats[4 * FINT + 2];  // sum_g, sq_g, sum_x, sq_x, s_sum, s_sq
__device__ float d_cf[4 * FINT];         // ag, ax, cc, psi_w
__device__ float d_ab[2];                // final sigmoid affine

__device__ __forceinline__ void ffma2(unsigned long long& d,
                                      unsigned long long a,
                                      unsigned long long b) {
    asm("fma.rn.f32x2 %0, %1, %2, %0;" : "+l"(d) : "l"(a), "l"(b));
}

__device__ __forceinline__ float2 ull2f2(unsigned long long v) {
    float2 r;
    asm("mov.b64 {%0, %1}, %2;" : "=f"(r.x), "=f"(r.y) : "l"(v));
    return r;
}

// ---------------------------------------------------------------------------
// GEMM: Y[o,p] = sum_c W[o,c]*X[b,c,hw] + bias[o], plus per-channel sum/sumsq.
// Block tile: 128 rows (all channels) x 128 pixels.  256 threads, 8x8/thread,
// accumulated as 8x4 packed f32x2 pairs via fma.rn.f32x2.
// ---------------------------------------------------------------------------
__global__ __launch_bounds__(256, 2)
void gemm_stats_kernel(const float* __restrict__ X,
                       const float* __restrict__ Wt,
                       const float* __restrict__ bias,
                       int path)
{
    __shared__ __align__(16) float2 Wp[KCH][FINT];  // W duplicated into (w,w) pairs
    __shared__ __align__(16) float  Xs[KCH][FINT];

    float* __restrict__ Y    = path ? d_Yx : d_Yg;
    float* __restrict__ ssum = d_stats + path * 256;
    float* __restrict__ ssq  = ssum + FINT;

    const int t  = threadIdx.x;
    const int tx = t & 15;
    const int ty = t >> 4;

    const int p0  = blockIdx.x * 128;
    const int b   = p0 >> 12;       // 4096 pixels per batch image; 4096 % 128 == 0
    const int hw0 = p0 & 4095;
    const float* Xb = X + (size_t)b * (CIN * HW4K) + hw0;

    unsigned long long acc[8][4];
    #pragma unroll
    for (int i = 0; i < 8; i++)
        #pragma unroll
        for (int j = 0; j < 4; j++) acc[i][j] = 0ULL;

    const int lkk = t >> 4;          // X loader: row within chunk
    const int lj  = (t & 15) * 8;    // X loader: col
    const int lo  = t >> 1;          // W loader: output channel
    const int lc  = (t & 1) * 8;     // W loader: c offset within chunk

    for (int c0 = 0; c0 < CIN; c0 += KCH) {
        // X chunk: [KCH][128], coalesced global reads
        const float* xg = Xb + (size_t)(c0 + lkk) * HW4K + lj;
        float4 xa = *(const float4*)(xg);
        float4 xb = *(const float4*)(xg + 4);
        *(float4*)&Xs[lkk][lj]     = xa;
        *(float4*)&Xs[lkk][lj + 4] = xb;

        // W chunk, duplicated into pairs so inner loop does pure LDS.128
        const float* wgp = Wt + lo * CIN + c0 + lc;
        float4 wa = *(const float4*)(wgp);
        float4 wb = *(const float4*)(wgp + 4);
        Wp[lc + 0][lo] = make_float2(wa.x, wa.x);
        Wp[lc + 1][lo] = make_float2(wa.y, wa.y);
        Wp[lc + 2][lo] = make_float2(wa.z, wa.z);
        Wp[lc + 3][lo] = make_float2(wa.w, wa.w);
        Wp[lc + 4][lo] = make_float2(wb.x, wb.x);
        Wp[lc + 5][lo] = make_float2(wb.y, wb.y);
        Wp[lc + 6][lo] = make_float2(wb.z, wb.z);
        Wp[lc + 7][lo] = make_float2(wb.w, wb.w);
        __syncthreads();

        #pragma unroll
        for (int kk = 0; kk < KCH; kk++) {
            const ulonglong2* wrow = (const ulonglong2*)&Wp[kk][ty * 8];
            ulonglong2 w01 = wrow[0];
            ulonglong2 w23 = wrow[1];
            ulonglong2 w45 = wrow[2];
            ulonglong2 w67 = wrow[3];
            const ulonglong2* xrow = (const ulonglong2*)&Xs[kk][tx * 8];
            ulonglong2 x01 = xrow[0];
            ulonglong2 x23 = xrow[1];
            unsigned long long wv[8] = {w01.x, w01.y, w23.x, w23.y,
                                        w45.x, w45.y, w67.x, w67.y};
            unsigned long long xv[4] = {x01.x, x01.y, x23.x, x23.y};
            #pragma unroll
            for (int i = 0; i < 8; i++)
                #pragma unroll
                for (int j = 0; j < 4; j++)
                    ffma2(acc[i][j], wv[i], xv[j]);
        }
        __syncthreads();
    }

    // Epilogue: add bias, store Y, reduce per-channel sum / sumsq.
    #pragma unroll
    for (int i = 0; i < 8; i++) {
        const int o = ty * 8 + i;
        const float bo = __ldg(&bias[o]);
        float2 v0 = ull2f2(acc[i][0]);
        float2 v1 = ull2f2(acc[i][1]);
        float2 v2 = ull2f2(acc[i][2]);
        float2 v3 = ull2f2(acc[i][3]);
        float y0 = v0.x + bo, y1 = v0.y + bo, y2 = v1.x + bo, y3 = v1.y + bo;
        float y4 = v2.x + bo, y5 = v2.y + bo, y6 = v3.x + bo, y7 = v3.y + bo;
        float* yp = Y + (size_t)o * NPIX + p0 + tx * 8;
        *(float4*)(yp)     = make_float4(y0, y1, y2, y3);
        *(float4*)(yp + 4) = make_float4(y4, y5, y6, y7);

        float rs = y0 + y1 + y2 + y3 + y4 + y5 + y6 + y7;
        float rq = y0*y0 + y1*y1 + y2*y2 + y3*y3 + y4*y4 + y5*y5 + y6*y6 + y7*y7;
        #pragma unroll
        for (int m = 8; m >= 1; m >>= 1) {
            rs += __shfl_xor_sync(0xFFFFFFFFu, rs, m);
            rq += __shfl_xor_sync(0xFFFFFFFFu, rq, m);
        }
        if (tx == 0) {  // lanes 0 and 16 (different ty / rows)
            atomicAdd(&ssum[o], rs);
            atomicAdd(&ssq[o], rq);
        }
    }
}

// ---------------------------------------------------------------------------
__global__ void zero_kernel() {
    for (int i = threadIdx.x; i < 4 * FINT + 2; i += 256) d_stats[i] = 0.0f;
}

__global__ void fin1_kernel(const float* __restrict__ wg_gamma,
                            const float* __restrict__ wg_beta,
                            const float* __restrict__ wx_gamma,
                            const float* __restrict__ wx_beta,
                            const float* __restrict__ psi_w)
{
    const int o = threadIdx.x;   // 128 threads
    const float n1 = 1.0f / (float)NPIX;
    float mg = d_stats[o] * n1;
    float vg = d_stats[FINT + o] * n1 - mg * mg;
    float ag = wg_gamma[o] * rsqrtf(vg + 1e-5f);
    float cg = wg_beta[o] - ag * mg;
    float mx = d_stats[2 * FINT + o] * n1;
    float vx = d_stats[3 * FINT + o] * n1 - mx * mx;
    float ax = wx_gamma[o] * rsqrtf(vx + 1e-5f);
    float cx = wx_beta[o] - ax * mx;
    d_cf[o]            = ag;
    d_cf[FINT + o]     = ax;
    d_cf[2 * FINT + o] = cg + cx;
    d_cf[3 * FINT + o] = psi_w[o];
}

// s[p] = sum_o psi_w[o] * relu(ag*yg + ax*yx + cc) + psi_b, plus global stats of s
__global__ __launch_bounds__(256)
void psi_kernel(const float* __restrict__ psi_b)
{
    __shared__ float ags[FINT], axs[FINT], ccs[FINT], pws[FINT];
    const int t = threadIdx.x;
    if (t < FINT) {
        ags[t] = d_cf[t];
        axs[t] = d_cf[FINT + t];
        ccs[t] = d_cf[2 * FINT + t];
        pws[t] = d_cf[3 * FINT + t];
    }
    __syncthreads();

    const int p = blockIdx.x * 256 + t;
    float acc = 0.0f;
    #pragma unroll 8
    for (int o = 0; o < FINT; o++) {
        float vg = d_Yg[(size_t)o * NPIX + p];
        float vx = d_Yx[(size_t)o * NPIX + p];
        float v  = fmaf(ags[o], vg, fmaf(axs[o], vx, ccs[o]));
        acc = fmaf(pws[o], fmaxf(v, 0.0f), acc);
    }
    acc += psi_b[0];
    d_S[p] = acc;

    float s = acc, q = acc * acc;
    #pragma unroll
    for (int m = 16; m >= 1; m >>= 1) {
        s += __shfl_xor_sync(0xFFFFFFFFu, s, m);
        q += __shfl_xor_sync(0xFFFFFFFFu, q, m);
    }
    __shared__ float ws[8], wq[8];
    const int lane = t & 31, w = t >> 5;
    if (lane == 0) { ws[w] = s; wq[w] = q; }
    __syncthreads();
    if (t == 0) {
        float ts = 0.0f, tq = 0.0f;
        #pragma unroll
        for (int i = 0; i < 8; i++) { ts += ws[i]; tq += wq[i]; }
        atomicAdd(&d_stats[4 * FINT + 0], ts);
        atomicAdd(&d_stats[4 * FINT + 1], tq);
    }
}

__global__ void fin2_kernel(const float* __restrict__ psi_gamma,
                            const float* __restrict__ psi_beta)
{
    const float n1 = 1.0f / (float)NPIX;
    float m = d_stats[4 * FINT + 0] * n1;
    float v = d_stats[4 * FINT + 1] * n1 - m * m;
    float a = psi_gamma[0] * rsqrtf(v + 1e-5f);
    d_ab[0] = a;
    d_ab[1] = psi_beta[0] - a * m;
}

// out[b,c,hw] = x[b,c,hw] * sigmoid(a*s[p] + c)
__global__ __launch_bounds__(256)
void out_kernel(const float* __restrict__ X, float* __restrict__ O)
{
    const size_t i = (size_t)blockIdx.x * 256 + threadIdx.x;
    const size_t e = i * 4;
    const int bidx = (int)(e >> 20);       // / (256*4096)
    const int hw   = (int)(e & 4095);
    const int p    = (bidx << 12) + hw;

    float4 xv = *(const float4*)(X + e);
    float4 sv = *(const float4*)(d_S + p);
    const float a = d_ab[0], c = d_ab[1];
    float4 r;
    r.x = xv.x / (1.0f + expf(-fmaf(a, sv.x, c)));
    r.y = xv.y / (1.0f + expf(-fmaf(a, sv.y, c)));
    r.z = xv.z / (1.0f + expf(-fmaf(a, sv.z, c)));
    r.w = xv.w / (1.0f + expf(-fmaf(a, sv.w, c)));
    *(float4*)(O + e) = r;
}

// ---------------------------------------------------------------------------
extern "C" void kernel_launch(void* const* d_in, const int* in_sizes, int n_in,
                              void* d_out, int out_size)
{
    const float* g         = (const float*)d_in[0];
    const float* x         = (const float*)d_in[1];
    const float* wg_w      = (const float*)d_in[2];
    const float* wg_b      = (const float*)d_in[3];
    const float* wg_gamma  = (const float*)d_in[4];
    const float* wg_beta   = (const float*)d_in[5];
    const float* wx_w      = (const float*)d_in[6];
    const float* wx_b      = (const float*)d_in[7];
    const float* wx_gamma  = (const float*)d_in[8];
    const float* wx_beta   = (const float*)d_in[9];
    const float* psi_w     = (const float*)d_in[10];
    const float* psi_b     = (const float*)d_in[11];
    const float* psi_gamma = (const float*)d_in[12];
    const float* psi_beta  = (const float*)d_in[13];
    float* out = (float*)d_out;

    zero_kernel<<<1, 256>>>();
    gemm_stats_kernel<<<NPIX / 128, 256>>>(g, wg_w, wg_b, 0);
    gemm_stats_kernel<<<NPIX / 128, 256>>>(x, wx_w, wx_b, 1);
    fin1_kernel<<<1, 128>>>(wg_gamma, wg_beta, wx_gamma, wx_beta, psi_w);
    psi_kernel<<<NPIX / 256, 256>>>(psi_b);
    fin2_kernel<<<1, 1>>>(psi_gamma, psi_beta);
    out_kernel<<<(16 * CIN * HW4K) / (4 * 256), 256>>>(x, out);
}

// round 3
// speedup vs baseline: 2.6124x; 2.6124x over previous
#include <cuda_runtime.h>

#define NPIX  65536
#define HW4K  4096
#define CIN   256
#define FINT  128
#define KC    16          // K-chunk for tensor GEMM

// Scratch (device globals — no runtime allocation allowed)
__device__ float d_Yg[FINT * NPIX];      // 33.5 MB
__device__ float d_Yx[FINT * NPIX];      // 33.5 MB
__device__ float d_S[NPIX];
__device__ float d_stats[4 * FINT + 2];  // sum_g, sq_g, sum_x, sq_x, s_sum, s_sq
__device__ float d_cf[4 * FINT];         // ag, ax, cc, psi_w
__device__ float d_ab[2];                // final sigmoid affine
__device__ float d_Wg_t[CIN * FINT];     // W_g transposed [c][o], tf32-rounded
__device__ float d_Wx_t[CIN * FINT];     // W_x transposed [c][o], tf32-rounded

// ---------------------------------------------------------------------------
// helpers
// ---------------------------------------------------------------------------
__device__ __forceinline__ unsigned f2tf(float f) {
    unsigned r;
    asm("cvt.rna.tf32.f32 %0, %1;" : "=r"(r) : "f"(f));
    return r;
}

__device__ __forceinline__ void mma8(float* c,
                                     unsigned a0, unsigned a1, unsigned a2, unsigned a3,
                                     unsigned b0, unsigned b1) {
    asm volatile(
        "mma.sync.aligned.m16n8k8.row.col.f32.tf32.tf32.f32 "
        "{%0,%1,%2,%3},{%4,%5,%6,%7},{%8,%9},{%0,%1,%2,%3};\n"
        : "+f"(c[0]), "+f"(c[1]), "+f"(c[2]), "+f"(c[3])
        : "r"(a0), "r"(a1), "r"(a2), "r"(a3), "r"(b0), "r"(b1));
}

__device__ __forceinline__ void cpa16(void* dst, const void* src) {
    unsigned d = (unsigned)__cvta_generic_to_shared(dst);
    asm volatile("cp.async.cg.shared.global [%0], [%1], 16;\n" :: "r"(d), "l"(src));
}
__device__ __forceinline__ void cpa_commit() {
    asm volatile("cp.async.commit_group;\n");
}

// ---------------------------------------------------------------------------
// prep: transpose + tf32-round both weight matrices:  W[o][c] -> Wt[c][o]
// ---------------------------------------------------------------------------
__global__ void prep_w_kernel(const float* __restrict__ wg,
                              const float* __restrict__ wx)
{
    const int i = blockIdx.x * 256 + threadIdx.x;   // 0..32767
    const int o = i >> 8;          // /256
    const int c = i & 255;
    d_Wg_t[c * FINT + o] = __uint_as_float(f2tf(wg[i]));
    d_Wx_t[c * FINT + o] = __uint_as_float(f2tf(wx[i]));
}

__global__ void zero_kernel() {
    for (int i = threadIdx.x; i < 4 * FINT + 2; i += 256) d_stats[i] = 0.0f;
}

// ---------------------------------------------------------------------------
// Tensor-core GEMM: Y[o,p] = sum_c W[o,c]*X[b,c,hw] + bias[o]  (tf32 mma)
// CTA: 128 channels x 128 pixels. 4 warps, each 64x64 (4 m16-tiles x 8 n8-tiles).
// K double-buffered in chunks of KC=16 via cp.async.
// Epilogue: bias add, store Y, per-channel sum/sumsq atomics.
// ---------------------------------------------------------------------------
__global__ __launch_bounds__(128, 2)
void gemm_tc_kernel(const float* __restrict__ X,
                    const float* __restrict__ Wt,   // [c][o] tf32
                    const float* __restrict__ bias,
                    int path)
{
    __shared__ float Ws[2][KC][132];
    __shared__ float Xs[2][KC][132];

    float* __restrict__ Y    = path ? d_Yx : d_Yg;
    float* __restrict__ ssum = d_stats + path * 256;
    float* __restrict__ ssq  = ssum + FINT;

    const int t    = threadIdx.x;
    const int lane = t & 31;
    const int wid  = t >> 5;
    const int g    = lane >> 2;    // group id (row within tile)
    const int tig  = lane & 3;     // thread in group
    const int m0w  = (wid >> 1) * 64;
    const int n0w  = (wid & 1) * 64;

    const int p0  = blockIdx.x * 128;
    const int b   = p0 >> 12;
    const int hw0 = p0 & 4095;
    const float* Xb = X + (size_t)b * (CIN * HW4K) + hw0;

    float acc[4][8][4];
    #pragma unroll
    for (int i = 0; i < 4; i++)
        #pragma unroll
        for (int j = 0; j < 8; j++)
            #pragma unroll
            for (int r = 0; r < 4; r++) acc[i][j][r] = 0.0f;

    // loader mapping: 512 float4 per operand chunk, 128 threads -> 4 each
    int lk[4], ln[4];
    #pragma unroll
    for (int r = 0; r < 4; r++) {
        int idx = t + 128 * r;
        lk[r] = idx >> 5;          // k row 0..15
        ln[r] = (idx & 31) * 4;    // col (float offset, 16B aligned)
    }

    // prologue: chunk 0 into buf 0
    #pragma unroll
    for (int r = 0; r < 4; r++) {
        cpa16(&Xs[0][lk[r]][ln[r]], Xb + (size_t)lk[r] * HW4K + ln[r]);
        cpa16(&Ws[0][lk[r]][ln[r]], Wt + lk[r] * FINT + ln[r]);
    }
    cpa_commit();

    const int NCH = CIN / KC;   // 16 chunks
    for (int ch = 0; ch < NCH; ch++) {
        const int buf = ch & 1;
        if (ch + 1 < NCH) {
            const int c0 = (ch + 1) * KC;
            #pragma unroll
            for (int r = 0; r < 4; r++) {
                cpa16(&Xs[buf ^ 1][lk[r]][ln[r]], Xb + (size_t)(c0 + lk[r]) * HW4K + ln[r]);
                cpa16(&Ws[buf ^ 1][lk[r]][ln[r]], Wt + (c0 + lk[r]) * FINT + ln[r]);
            }
            cpa_commit();
            asm volatile("cp.async.wait_group 1;\n");
        } else {
            asm volatile("cp.async.wait_group 0;\n");
        }
        __syncthreads();

        #pragma unroll
        for (int ks = 0; ks < KC / 8; ks++) {
            const int k0 = ks * 8;
            // B fragments (pixels), convert to tf32 RNA
            unsigned bf[8][2];
            #pragma unroll
            for (int j = 0; j < 8; j++) {
                bf[j][0] = f2tf(Xs[buf][k0 + tig][n0w + 8 * j + g]);
                bf[j][1] = f2tf(Xs[buf][k0 + tig + 4][n0w + 8 * j + g]);
            }
            #pragma unroll
            for (int i = 0; i < 4; i++) {
                const int m0 = m0w + 16 * i;
                unsigned a0 = __float_as_uint(Ws[buf][k0 + tig][m0 + g]);
                unsigned a1 = __float_as_uint(Ws[buf][k0 + tig][m0 + g + 8]);
                unsigned a2 = __float_as_uint(Ws[buf][k0 + tig + 4][m0 + g]);
                unsigned a3 = __float_as_uint(Ws[buf][k0 + tig + 4][m0 + g + 8]);
                #pragma unroll
                for (int j = 0; j < 8; j++)
                    mma8(acc[i][j], a0, a1, a2, a3, bf[j][0], bf[j][1]);
            }
        }
        __syncthreads();
    }

    // Epilogue: bias, store Y, per-channel stats
    #pragma unroll
    for (int i = 0; i < 4; i++) {
        const int r0 = m0w + 16 * i + g;
        const int r1 = r0 + 8;
        const float b0v = __ldg(&bias[r0]);
        const float b1v = __ldg(&bias[r1]);
        float s0 = 0.f, q0 = 0.f, s1 = 0.f, q1 = 0.f;
        #pragma unroll
        for (int j = 0; j < 8; j++) {
            float y00 = acc[i][j][0] + b0v, y01 = acc[i][j][1] + b0v;
            float y10 = acc[i][j][2] + b1v, y11 = acc[i][j][3] + b1v;
            const int col = p0 + n0w + 8 * j + 2 * tig;
            *(float2*)&Y[(size_t)r0 * NPIX + col] = make_float2(y00, y01);
            *(float2*)&Y[(size_t)r1 * NPIX + col] = make_float2(y10, y11);
            s0 += y00 + y01;  q0 += y00 * y00 + y01 * y01;
            s1 += y10 + y11;  q1 += y10 * y10 + y11 * y11;
        }
        // reduce across the 4 lanes of this group (tig 0..3)
        #pragma unroll
        for (int m = 1; m <= 2; m <<= 1) {
            s0 += __shfl_xor_sync(0xFFFFFFFFu, s0, m);
            q0 += __shfl_xor_sync(0xFFFFFFFFu, q0, m);
            s1 += __shfl_xor_sync(0xFFFFFFFFu, s1, m);
            q1 += __shfl_xor_sync(0xFFFFFFFFu, q1, m);
        }
        if (tig == 0) {
            atomicAdd(&ssum[r0], s0);
            atomicAdd(&ssq[r0],  q0);
            atomicAdd(&ssum[r1], s1);
            atomicAdd(&ssq[r1],  q1);
        }
    }
}

// ---------------------------------------------------------------------------
__global__ void fin1_kernel(const float* __restrict__ wg_gamma,
                            const float* __restrict__ wg_beta,
                            const float* __restrict__ wx_gamma,
                            const float* __restrict__ wx_beta,
                            const float* __restrict__ psi_w)
{
    const int o = threadIdx.x;   // 128 threads
    const float n1 = 1.0f / (float)NPIX;
    float mg = d_stats[o] * n1;
    float vg = d_stats[FINT + o] * n1 - mg * mg;
    float ag = wg_gamma[o] * rsqrtf(vg + 1e-5f);
    float cg = wg_beta[o] - ag * mg;
    float mx = d_stats[2 * FINT + o] * n1;
    float vx = d_stats[3 * FINT + o] * n1 - mx * mx;
    float ax = wx_gamma[o] * rsqrtf(vx + 1e-5f);
    float cx = wx_beta[o] - ax * mx;
    d_cf[o]            = ag;
    d_cf[FINT + o]     = ax;
    d_cf[2 * FINT + o] = cg + cx;
    d_cf[3 * FINT + o] = psi_w[o];
}

// s[p] = sum_o psi_w[o] * relu(ag*yg + ax*yx + cc) + psi_b, plus global stats of s
__global__ __launch_bounds__(256)
void psi_kernel(const float* __restrict__ psi_b)
{
    __shared__ float ags[FINT], axs[FINT], ccs[FINT], pws[FINT];
    const int t = threadIdx.x;
    if (t < FINT) {
        ags[t] = d_cf[t];
        axs[t] = d_cf[FINT + t];
        ccs[t] = d_cf[2 * FINT + t];
        pws[t] = d_cf[3 * FINT + t];
    }
    __syncthreads();

    const int p = blockIdx.x * 256 + t;
    float acc = 0.0f;
    #pragma unroll 8
    for (int o = 0; o < FINT; o++) {
        float vg = d_Yg[(size_t)o * NPIX + p];
        float vx = d_Yx[(size_t)o * NPIX + p];
        float v  = fmaf(ags[o], vg, fmaf(axs[o], vx, ccs[o]));
        acc = fmaf(pws[o], fmaxf(v, 0.0f), acc);
    }
    acc += psi_b[0];
    d_S[p] = acc;

    float s = acc, q = acc * acc;
    #pragma unroll
    for (int m = 16; m >= 1; m >>= 1) {
        s += __shfl_xor_sync(0xFFFFFFFFu, s, m);
        q += __shfl_xor_sync(0xFFFFFFFFu, q, m);
    }
    __shared__ float ws[8], wq[8];
    const int lane = t & 31, w = t >> 5;
    if (lane == 0) { ws[w] = s; wq[w] = q; }
    __syncthreads();
    if (t == 0) {
        float ts = 0.0f, tq = 0.0f;
        #pragma unroll
        for (int i = 0; i < 8; i++) { ts += ws[i]; tq += wq[i]; }
        atomicAdd(&d_stats[4 * FINT + 0], ts);
        atomicAdd(&d_stats[4 * FINT + 1], tq);
    }
}

__global__ void fin2_kernel(const float* __restrict__ psi_gamma,
                            const float* __restrict__ psi_beta)
{
    const float n1 = 1.0f / (float)NPIX;
    float m = d_stats[4 * FINT + 0] * n1;
    float v = d_stats[4 * FINT + 1] * n1 - m * m;
    float a = psi_gamma[0] * rsqrtf(v + 1e-5f);
    d_ab[0] = a;
    d_ab[1] = psi_beta[0] - a * m;
}

// out[b,c,hw] = x[b,c,hw] * sigmoid(a*s[p] + c)
__global__ __launch_bounds__(256)
void out_kernel(const float* __restrict__ X, float* __restrict__ O)
{
    const size_t i = (size_t)blockIdx.x * 256 + threadIdx.x;
    const size_t e = i * 4;
    const int bidx = (int)(e >> 20);       // / (256*4096)
    const int hw   = (int)(e & 4095);
    const int p    = (bidx << 12) + hw;

    float4 xv = *(const float4*)(X + e);
    float4 sv = *(const float4*)(d_S + p);
    const float a = d_ab[0], c = d_ab[1];
    float4 r;
    r.x = xv.x / (1.0f + expf(-fmaf(a, sv.x, c)));
    r.y = xv.y / (1.0f + expf(-fmaf(a, sv.y, c)));
    r.z = xv.z / (1.0f + expf(-fmaf(a, sv.z, c)));
    r.w = xv.w / (1.0f + expf(-fmaf(a, sv.w, c)));
    *(float4*)(O + e) = r;
}

// ---------------------------------------------------------------------------
extern "C" void kernel_launch(void* const* d_in, const int* in_sizes, int n_in,
                              void* d_out, int out_size)
{
    const float* g         = (const float*)d_in[0];
    const float* x         = (const float*)d_in[1];
    const float* wg_w      = (const float*)d_in[2];
    const float* wg_b      = (const float*)d_in[3];
    const float* wg_gamma  = (const float*)d_in[4];
    const float* wg_beta   = (const float*)d_in[5];
    const float* wx_w      = (const float*)d_in[6];
    const float* wx_b      = (const float*)d_in[7];
    const float* wx_gamma  = (const float*)d_in[8];
    const float* wx_beta   = (const float*)d_in[9];
    const float* psi_w     = (const float*)d_in[10];
    const float* psi_b     = (const float*)d_in[11];
    const float* psi_gamma = (const float*)d_in[12];
    const float* psi_beta  = (const float*)d_in[13];
    float* out = (float*)d_out;

    zero_kernel<<<1, 256>>>();
    prep_w_kernel<<<(FINT * CIN) / 256, 256>>>(wg_w, wx_w);

    float* d_Wg_t_p = nullptr; float* d_Wx_t_p = nullptr;
    cudaGetSymbolAddress((void**)&d_Wg_t_p, d_Wg_t);
    cudaGetSymbolAddress((void**)&d_Wx_t_p, d_Wx_t);

    gemm_tc_kernel<<<NPIX / 128, 128>>>(g, d_Wg_t_p, wg_b, 0);
    gemm_tc_kernel<<<NPIX / 128, 128>>>(x, d_Wx_t_p, wx_b, 1);
    fin1_kernel<<<1, 128>>>(wg_gamma, wg_beta, wx_gamma, wx_beta, psi_w);
    psi_kernel<<<NPIX / 256, 256>>>(psi_b);
    fin2_kernel<<<1, 1>>>(psi_gamma, psi_beta);
    out_kernel<<<(16 * CIN * HW4K) / (4 * 256), 256>>>(x, out);
}

// round 4
// speedup vs baseline: 2.6879x; 1.0289x over previous
#include <cuda_runtime.h>

#define NPIX  65536
#define HW4K  4096
#define CIN   256
#define FINT  128
#define KC    16          // K-chunk for tensor GEMM
#define SROW  136         // smem row stride (floats): bank = 8*tig + g, conflict-free

// Scratch (device globals — no runtime allocation allowed)
__device__ float d_Yg[FINT * NPIX];      // 33.5 MB
__device__ float d_Yx[FINT * NPIX];      // 33.5 MB
__device__ float d_S[NPIX];
__device__ float d_stats[4 * FINT + 2];  // sum_g, sq_g, sum_x, sq_x, s_sum, s_sq
__device__ float d_cf[4 * FINT];         // ag, ax, cc, psi_w
__device__ float d_ab[2];                // final sigmoid affine
__device__ float d_Wg_t[CIN * FINT];     // W_g transposed [c][o], tf32-rounded
__device__ float d_Wx_t[CIN * FINT];     // W_x transposed [c][o], tf32-rounded

// ---------------------------------------------------------------------------
// helpers
// ---------------------------------------------------------------------------
__device__ __forceinline__ unsigned f2tf(float f) {
    unsigned r;
    asm("cvt.rna.tf32.f32 %0, %1;" : "=r"(r) : "f"(f));
    return r;
}

__device__ __forceinline__ void mma8(float* c,
                                     unsigned a0, unsigned a1, unsigned a2, unsigned a3,
                                     unsigned b0, unsigned b1) {
    asm volatile(
        "mma.sync.aligned.m16n8k8.row.col.f32.tf32.tf32.f32 "
        "{%0,%1,%2,%3},{%4,%5,%6,%7},{%8,%9},{%0,%1,%2,%3};\n"
        : "+f"(c[0]), "+f"(c[1]), "+f"(c[2]), "+f"(c[3])
        : "r"(a0), "r"(a1), "r"(a2), "r"(a3), "r"(b0), "r"(b1));
}

__device__ __forceinline__ void cpa16(void* dst, const void* src) {
    unsigned d = (unsigned)__cvta_generic_to_shared(dst);
    asm volatile("cp.async.cg.shared.global [%0], [%1], 16;\n" :: "r"(d), "l"(src));
}
__device__ __forceinline__ void cpa_commit() {
    asm volatile("cp.async.commit_group;\n");
}

// ---------------------------------------------------------------------------
// prep: transpose + tf32-round both weight matrices (W[o][c] -> Wt[c][o]);
// block 0 also zeroes the stats accumulators.
// ---------------------------------------------------------------------------
__global__ void prep_w_kernel(const float* __restrict__ wg,
                              const float* __restrict__ wx)
{
    const int i = blockIdx.x * 256 + threadIdx.x;   // 0..32767
    const int o = i >> 8;
    const int c = i & 255;
    d_Wg_t[c * FINT + o] = __uint_as_float(f2tf(wg[i]));
    d_Wx_t[c * FINT + o] = __uint_as_float(f2tf(wx[i]));
    if (blockIdx.x == 0) {
        for (int k = threadIdx.x; k < 4 * FINT + 2; k += 256) d_stats[k] = 0.0f;
    }
}

// ---------------------------------------------------------------------------
// Tensor-core GEMM: Y[o,p] = sum_c W[o,c]*X[b,c,hw] + bias[o]  (tf32 mma)
// CTA: 128 channels x 128 pixels, 8 warps, warp tile 32(ch) x 64(px).
// K double-buffered in chunks of KC=16 via cp.async. 2 CTAs/SM (16 warps).
// Epilogue: bias add, store Y, per-channel sum/sumsq atomics.
// ---------------------------------------------------------------------------
__global__ __launch_bounds__(256, 2)
void gemm_tc_kernel(const float* __restrict__ X,
                    const float* __restrict__ Wt,   // [c][o] tf32
                    const float* __restrict__ bias,
                    int path)
{
    __shared__ __align__(16) float Ws[2][KC][SROW];
    __shared__ __align__(16) float Xs[2][KC][SROW];

    float* __restrict__ Y    = path ? d_Yx : d_Yg;
    float* __restrict__ ssum = d_stats + path * 256;
    float* __restrict__ ssq  = ssum + FINT;

    const int t    = threadIdx.x;
    const int lane = t & 31;
    const int wid  = t >> 5;         // 0..7
    const int g    = lane >> 2;      // 0..7
    const int tig  = lane & 3;       // 0..3
    const int m0w  = (wid >> 1) * 32;   // 4 m-warps
    const int n0w  = (wid & 1) * 64;    // 2 n-warps

    const int p0  = blockIdx.x * 128;
    const int b   = p0 >> 12;
    const int hw0 = p0 & 4095;
    const float* Xb = X + (size_t)b * (CIN * HW4K) + hw0;

    float acc[2][8][4];
    #pragma unroll
    for (int i = 0; i < 2; i++)
        #pragma unroll
        for (int j = 0; j < 8; j++)
            #pragma unroll
            for (int r = 0; r < 4; r++) acc[i][j][r] = 0.0f;

    // loader: per chunk per operand 512 float4; 256 threads -> 2 each
    int lk[2], ln[2];
    #pragma unroll
    for (int r = 0; r < 2; r++) {
        int idx = t + 256 * r;
        lk[r] = idx >> 5;            // k row 0..15
        ln[r] = (idx & 31) * 4;      // col (float offset, 16B aligned)
    }

    // prologue: chunk 0 into buf 0
    #pragma unroll
    for (int r = 0; r < 2; r++) {
        cpa16(&Xs[0][lk[r]][ln[r]], Xb + (size_t)lk[r] * HW4K + ln[r]);
        cpa16(&Ws[0][lk[r]][ln[r]], Wt + lk[r] * FINT + ln[r]);
    }
    cpa_commit();

    const int NCH = CIN / KC;   // 16 chunks
    for (int ch = 0; ch < NCH; ch++) {
        const int buf = ch & 1;
        if (ch + 1 < NCH) {
            const int c0 = (ch + 1) * KC;
            #pragma unroll
            for (int r = 0; r < 2; r++) {
                cpa16(&Xs[buf ^ 1][lk[r]][ln[r]], Xb + (size_t)(c0 + lk[r]) * HW4K + ln[r]);
                cpa16(&Ws[buf ^ 1][lk[r]][ln[r]], Wt + (c0 + lk[r]) * FINT + ln[r]);
            }
            cpa_commit();
            asm volatile("cp.async.wait_group 1;\n");
        } else {
            asm volatile("cp.async.wait_group 0;\n");
        }
        __syncthreads();

        #pragma unroll
        for (int ks = 0; ks < KC / 8; ks++) {
            const int k0 = ks * 8;
            // B fragments (pixels): conflict-free (bank = 8*tig + g)
            unsigned bf[8][2];
            #pragma unroll
            for (int j = 0; j < 8; j++) {
                bf[j][0] = f2tf(Xs[buf][k0 + tig][n0w + 8 * j + g]);
                bf[j][1] = f2tf(Xs[buf][k0 + tig + 4][n0w + 8 * j + g]);
            }
            #pragma unroll
            for (int i = 0; i < 2; i++) {
                const int m0 = m0w + 16 * i;
                unsigned a0 = __float_as_uint(Ws[buf][k0 + tig][m0 + g]);
                unsigned a1 = __float_as_uint(Ws[buf][k0 + tig][m0 + g + 8]);
                unsigned a2 = __float_as_uint(Ws[buf][k0 + tig + 4][m0 + g]);
                unsigned a3 = __float_as_uint(Ws[buf][k0 + tig + 4][m0 + g + 8]);
                #pragma unroll
                for (int j = 0; j < 8; j++)
                    mma8(acc[i][j], a0, a1, a2, a3, bf[j][0], bf[j][1]);
            }
        }
        __syncthreads();
    }

    // Epilogue: bias, store Y, per-channel stats
    #pragma unroll
    for (int i = 0; i < 2; i++) {
        const int r0 = m0w + 16 * i + g;
        const int r1 = r0 + 8;
        const float b0v = __ldg(&bias[r0]);
        const float b1v = __ldg(&bias[r1]);
        float s0 = 0.f, q0 = 0.f, s1 = 0.f, q1 = 0.f;
        #pragma unroll
        for (int j = 0; j < 8; j++) {
            float y00 = acc[i][j][0] + b0v, y01 = acc[i][j][1] + b0v;
            float y10 = acc[i][j][2] + b1v, y11 = acc[i][j][3] + b1v;
            const int col = p0 + n0w + 8 * j + 2 * tig;
            *(float2*)&Y[(size_t)r0 * NPIX + col] = make_float2(y00, y01);
            *(float2*)&Y[(size_t)r1 * NPIX + col] = make_float2(y10, y11);
            s0 += y00 + y01;  q0 += y00 * y00 + y01 * y01;
            s1 += y10 + y11;  q1 += y10 * y10 + y11 * y11;
        }
        // reduce across tig (lanes xor 1, 2)
        #pragma unroll
        for (int m = 1; m <= 2; m <<= 1) {
            s0 += __shfl_xor_sync(0xFFFFFFFFu, s0, m);
            q0 += __shfl_xor_sync(0xFFFFFFFFu, q0, m);
            s1 += __shfl_xor_sync(0xFFFFFFFFu, s1, m);
            q1 += __shfl_xor_sync(0xFFFFFFFFu, q1, m);
        }
        if (tig == 0) {
            atomicAdd(&ssum[r0], s0);
            atomicAdd(&ssq[r0],  q0);
            atomicAdd(&ssum[r1], s1);
            atomicAdd(&ssq[r1],  q1);
        }
    }
}

// ---------------------------------------------------------------------------
__global__ void fin1_kernel(const float* __restrict__ wg_gamma,
                            const float* __restrict__ wg_beta,
                            const float* __restrict__ wx_gamma,
                            const float* __restrict__ wx_beta,
                            const float* __restrict__ psi_w)
{
    const int o = threadIdx.x;   // 128 threads
    const float n1 = 1.0f / (float)NPIX;
    float mg = d_stats[o] * n1;
    float vg = d_stats[FINT + o] * n1 - mg * mg;
    float ag = wg_gamma[o] * rsqrtf(vg + 1e-5f);
    float cg = wg_beta[o] - ag * mg;
    float mx = d_stats[2 * FINT + o] * n1;
    float vx = d_stats[3 * FINT + o] * n1 - mx * mx;
    float ax = wx_gamma[o] * rsqrtf(vx + 1e-5f);
    float cx = wx_beta[o] - ax * mx;
    d_cf[o]            = ag;
    d_cf[FINT + o]     = ax;
    d_cf[2 * FINT + o] = cg + cx;
    d_cf[3 * FINT + o] = psi_w[o];
}

// s[p] = sum_o psi_w[o] * relu(ag*yg + ax*yx + cc) + psi_b, plus global stats of s
__global__ __launch_bounds__(256)
void psi_kernel(const float* __restrict__ psi_b)
{
    __shared__ float ags[FINT], axs[FINT], ccs[FINT], pws[FINT];
    const int t = threadIdx.x;
    if (t < FINT) {
        ags[t] = d_cf[t];
        axs[t] = d_cf[FINT + t];
        ccs[t] = d_cf[2 * FINT + t];
        pws[t] = d_cf[3 * FINT + t];
    }
    __syncthreads();

    const int p = blockIdx.x * 256 + t;
    float acc = 0.0f;
    #pragma unroll 8
    for (int o = 0; o < FINT; o++) {
        float vg = d_Yg[(size_t)o * NPIX + p];
        float vx = d_Yx[(size_t)o * NPIX + p];
        float v  = fmaf(ags[o], vg, fmaf(axs[o], vx, ccs[o]));
        acc = fmaf(pws[o], fmaxf(v, 0.0f), acc);
    }
    acc += psi_b[0];
    d_S[p] = acc;

    float s = acc, q = acc * acc;
    #pragma unroll
    for (int m = 16; m >= 1; m >>= 1) {
        s += __shfl_xor_sync(0xFFFFFFFFu, s, m);
        q += __shfl_xor_sync(0xFFFFFFFFu, q, m);
    }
    __shared__ float ws[8], wq[8];
    const int lane = t & 31, w = t >> 5;
    if (lane == 0) { ws[w] = s; wq[w] = q; }
    __syncthreads();
    if (t == 0) {
        float ts = 0.0f, tq = 0.0f;
        #pragma unroll
        for (int i = 0; i < 8; i++) { ts += ws[i]; tq += wq[i]; }
        atomicAdd(&d_stats[4 * FINT + 0], ts);
        atomicAdd(&d_stats[4 * FINT + 1], tq);
    }
}

__global__ void fin2_kernel(const float* __restrict__ psi_gamma,
                            const float* __restrict__ psi_beta)
{
    const float n1 = 1.0f / (float)NPIX;
    float m = d_stats[4 * FINT + 0] * n1;
    float v = d_stats[4 * FINT + 1] * n1 - m * m;
    float a = psi_gamma[0] * rsqrtf(v + 1e-5f);
    d_ab[0] = a;
    d_ab[1] = psi_beta[0] - a * m;
}

// out[b,c,hw] = x[b,c,hw] * sigmoid(a*s[p] + c)
__global__ __launch_bounds__(256)
void out_kernel(const float* __restrict__ X, float* __restrict__ O)
{
    const size_t i = (size_t)blockIdx.x * 256 + threadIdx.x;
    const size_t e = i * 4;
    const int bidx = (int)(e >> 20);       // / (256*4096)
    const int hw   = (int)(e & 4095);
    const int p    = (bidx << 12) + hw;

    float4 xv = *(const float4*)(X + e);
    float4 sv = *(const float4*)(d_S + p);
    const float a = d_ab[0], c = d_ab[1];
    float4 r;
    r.x = xv.x / (1.0f + expf(-fmaf(a, sv.x, c)));
    r.y = xv.y / (1.0f + expf(-fmaf(a, sv.y, c)));
    r.z = xv.z / (1.0f + expf(-fmaf(a, sv.z, c)));
    r.w = xv.w / (1.0f + expf(-fmaf(a, sv.w, c)));
    *(float4*)(O + e) = r;
}

// ---------------------------------------------------------------------------
extern "C" void kernel_launch(void* const* d_in, const int* in_sizes, int n_in,
                              void* d_out, int out_size)
{
    const float* g         = (const float*)d_in[0];
    const float* x         = (const float*)d_in[1];
    const float* wg_w      = (const float*)d_in[2];
    const float* wg_b      = (const float*)d_in[3];
    const float* wg_gamma  = (const float*)d_in[4];
    const float* wg_beta   = (const float*)d_in[5];
    const float* wx_w      = (const float*)d_in[6];
    const float* wx_b      = (const float*)d_in[7];
    const float* wx_gamma  = (const float*)d_in[8];
    const float* wx_beta   = (const float*)d_in[9];
    const float* psi_w     = (const float*)d_in[10];
    const float* psi_b     = (const float*)d_in[11];
    const float* psi_gamma = (const float*)d_in[12];
    const float* psi_beta  = (const float*)d_in[13];
    float* out = (float*)d_out;

    prep_w_kernel<<<(FINT * CIN) / 256, 256>>>(wg_w, wx_w);

    float* d_Wg_t_p = nullptr; float* d_Wx_t_p = nullptr;
    cudaGetSymbolAddress((void**)&d_Wg_t_p, d_Wg_t);
    cudaGetSymbolAddress((void**)&d_Wx_t_p, d_Wx_t);

    gemm_tc_kernel<<<NPIX / 128, 256>>>(g, d_Wg_t_p, wg_b, 0);
    gemm_tc_kernel<<<NPIX / 128, 256>>>(x, d_Wx_t_p, wx_b, 1);
    fin1_kernel<<<1, 128>>>(wg_gamma, wg_beta, wx_gamma, wx_beta, psi_w);
    psi_kernel<<<NPIX / 256, 256>>>(psi_b);
    fin2_kernel<<<1, 1>>>(psi_gamma, psi_beta);
    out_kernel<<<(16 * CIN * HW4K) / (4 * 256), 256>>>(x, out);
}